// round 13
// baseline (speedup 1.0000x reference)
#include <cuda_runtime.h>

#define BB 4
#define CC 64
#define HH 256
#define WW 256
#define HW (HH*WW)
#define CHW (CC*HW)

#define NSPLIT 8
#define ECH (CC/NSPLIT)   // 8 channels per edge block
#define BCH 8             // channels per blur block

#define SIGMA_MIN 0.6f
#define SIGMA_MAX 1.2f

// Scratch (static device allocations — no cudaMalloc allowed)
__device__ float d_edge[BB*HW];                  // 1 MB
__device__ float d_edge_part[NSPLIT][BB*HW];     // 8 MB partial channel-sums
__device__ float d_g[4][BB*HW];                  // 4 MB (symmetric taps)
__device__ float d_tmp[(size_t)BB*CHW];          // 64 MB horizontal-pass result
__device__ unsigned int d_minmax[2*BB];          // per-batch {min,max} uint bits

__global__ void init_minmax_kernel() {
    int i = threadIdx.x;
    if (i < BB) {
        d_minmax[2*i]   = 0x7f800000u; // +inf
        d_minmax[2*i+1] = 0u;          // 0
    }
}

// Partial Sobel edge-energy sums over 8 channels per block.
// v3: thread = 4 consecutive output rows x 4 cols; per channel a 6-row
// register window (6 LDG.128 + edge scalars, MLP~18). No smem, no barriers.
__global__ __launch_bounds__(256) void edge_partial_kernel(const float* __restrict__ x) {
    const int tx = threadIdx.x;              // 0..63 (column quad)
    const int ty = threadIdx.y;              // 0..3  (4-row group)
    const int h0 = blockIdx.x*16 + ty*4;     // first output row
    const int sp = blockIdx.y;               // channel split
    const int b  = blockIdx.z;
    const int w4 = tx*4;

    const float* xb = x + (size_t)b*CHW + (size_t)sp*ECH*HW + w4;
    const bool hasL = (tx > 0), hasR = (tx < 63);

    float acc[4][4] = {};

    for (int c = 0; c < ECH; c++) {
        const float* pc = xb + (size_t)c*HW;
        float d[6][4], s[6][4];

        #pragma unroll
        for (int r = 0; r < 6; r++) {
            const int gh = h0 - 1 + r;
            float4 m = make_float4(0.f, 0.f, 0.f, 0.f);
            float l = 0.f, rt = 0.f;
            if (gh >= 0 && gh < HH) {
                const float* p = pc + gh*WW;
                m  = *(const float4*)p;
                l  = hasL ? p[-1] : 0.f;
                rt = hasR ? p[4]  : 0.f;
            }
            d[r][0] = m.y - l;    s[r][0] = l   + 2.f*m.x + m.y;
            d[r][1] = m.z - m.x;  s[r][1] = m.x + 2.f*m.y + m.z;
            d[r][2] = m.w - m.y;  s[r][2] = m.y + 2.f*m.z + m.w;
            d[r][3] = rt  - m.z;  s[r][3] = m.z + 2.f*m.w + rt;
        }

        #pragma unroll
        for (int j = 0; j < 4; j++) {
            #pragma unroll
            for (int k = 0; k < 4; k++) {
                float gx = d[j][k] + 2.f*d[j+1][k] + d[j+2][k];
                float gy = s[j+2][k] - s[j][k];
                acc[j][k] = fmaf(gx, gx, acc[j][k]);
                acc[j][k] = fmaf(gy, gy, acc[j][k]);
            }
        }
    }

    #pragma unroll
    for (int j = 0; j < 4; j++) {
        float4 e = make_float4(acc[j][0], acc[j][1], acc[j][2], acc[j][3]);
        *(float4*)(d_edge_part[sp] + b*HW + (h0 + j)*WW + w4) = e;
    }
}

// Sum partials -> edge; per-batch min/max via block reduce + uint atomics.
__global__ __launch_bounds__(256) void edge_reduce_kernel() {
    __shared__ float smin[8], smax[8];
    const int idx4 = blockIdx.x*256 + threadIdx.x;
    const int b = idx4 >> 14;

    float4 s = make_float4(0.f, 0.f, 0.f, 0.f);
    #pragma unroll
    for (int sp = 0; sp < NSPLIT; sp++) {
        float4 v = *(const float4*)(d_edge_part[sp] + (size_t)idx4*4);
        s.x += v.x; s.y += v.y; s.z += v.z; s.w += v.w;
    }
    s.x *= (1.f/64.f); s.y *= (1.f/64.f); s.z *= (1.f/64.f); s.w *= (1.f/64.f);
    *(float4*)(d_edge + (size_t)idx4*4) = s;

    float vmin = fminf(fminf(s.x, s.y), fminf(s.z, s.w));
    float vmax = fmaxf(fmaxf(s.x, s.y), fmaxf(s.z, s.w));
    #pragma unroll
    for (int o = 16; o; o >>= 1) {
        vmin = fminf(vmin, __shfl_xor_sync(0xffffffffu, vmin, o));
        vmax = fmaxf(vmax, __shfl_xor_sync(0xffffffffu, vmax, o));
    }
    const int wid = threadIdx.x >> 5, lane = threadIdx.x & 31;
    if (lane == 0) { smin[wid] = vmin; smax[wid] = vmax; }
    __syncthreads();
    if (threadIdx.x == 0) {
        float m = smin[0], M = smax[0];
        #pragma unroll
        for (int i = 1; i < 8; i++) { m = fminf(m, smin[i]); M = fmaxf(M, smax[i]); }
        atomicMin(&d_minmax[2*b],   __float_as_uint(m));
        atomicMax(&d_minmax[2*b+1], __float_as_uint(M));
    }
}

// Per-pixel normalized Gaussian taps. 1 expf per pixel; scalar = max parallelism.
__global__ __launch_bounds__(256) void gauss_kernel() {
    const int idx = blockIdx.x*256 + threadIdx.x;
    const int b = idx >> 16;   // HW per batch
    const float emin = __uint_as_float(d_minmax[2*b]);
    const float rden = __fdividef(1.f, __uint_as_float(d_minmax[2*b+1]) + 1e-6f);

    float e = (d_edge[idx] - emin) * rden;
    float s = SIGMA_MIN + (SIGMA_MAX - SIGMA_MIN)*e;
    float t = __fdividef(1.f, s);
    float inv = 0.5f*t*t;
    float w2 = __expf(-inv);
    float w2_2 = w2*w2;
    float w1 = w2_2*w2_2;
    float w0 = w1*w1*w2;
    float r = __fdividef(1.f, 2.f*(w0 + w1 + w2) + 1.f);
    d_g[0][idx] = w0*r;
    d_g[1][idx] = w1*r;
    d_g[2][idx] = w2*r;
    d_g[3][idx] = r;
}

// Horizontal pass: thread = 4 outputs x 8 channels; g in regs; no barriers.
__global__ __launch_bounds__(256) void hblur_kernel(const float* __restrict__ x) {
    const int tx = threadIdx.x;                 // 0..63
    const int h  = blockIdx.x*4 + threadIdx.y;
    const int c0 = blockIdx.y*BCH;
    const int b  = blockIdx.z;
    const int w4 = tx*4;
    const int pidx = b*HW + h*WW + w4;

    const float4 G0 = *(const float4*)&d_g[0][pidx];
    const float4 G1 = *(const float4*)&d_g[1][pidx];
    const float4 G2 = *(const float4*)&d_g[2][pidx];
    const float4 G3 = *(const float4*)&d_g[3][pidx];

    const float* xr = x     + (size_t)b*CHW + (size_t)c0*HW + h*WW + w4;
    float*       tr = d_tmp + (size_t)b*CHW + (size_t)c0*HW + h*WW + w4;
    const bool hasL = (tx > 0), hasR = (tx < 63);
    const float4 z4 = make_float4(0.f, 0.f, 0.f, 0.f);

    #pragma unroll 2
    for (int c = 0; c < BCH; c++) {
        const float* p = xr + (size_t)c*HW;
        float4 m  = *(const float4*)p;
        float4 lf = hasL ? *(const float4*)(p - 4) : z4;
        float4 rf = hasR ? *(const float4*)(p + 4) : z4;
        float v0=lf.y, v1=lf.z, v2=lf.w, v3=m.x, v4=m.y, v5=m.z, v6=m.w, v7=rf.x, v8=rf.y, v9=rf.z;
        float4 o;
        o.x = fmaf(G0.x, v0+v6, fmaf(G1.x, v1+v5, fmaf(G2.x, v2+v4, G3.x*v3)));
        o.y = fmaf(G0.y, v1+v7, fmaf(G1.y, v2+v6, fmaf(G2.y, v3+v5, G3.y*v4)));
        o.z = fmaf(G0.z, v2+v8, fmaf(G1.z, v3+v7, fmaf(G2.z, v4+v6, G3.z*v5)));
        o.w = fmaf(G0.w, v3+v9, fmaf(G1.w, v4+v8, fmaf(G2.w, v5+v7, G3.w*v6)));
        *(float4*)(tr + (size_t)c*HW) = o;
    }
}

// Vertical pass: thread = 4 consecutive output rows x 8 channels.
// Per channel: 10-row register window (10 LDG.128) -> 4 outputs (4 STG.128).
__global__ __launch_bounds__(256) void vblur_kernel(float* __restrict__ out) {
    const int tx = threadIdx.x;                      // 0..63 (column quad)
    const int ty = threadIdx.y;                      // 0..3 (4-row group)
    const int h0 = blockIdx.x*16 + ty*4;             // first output row
    const int c0 = blockIdx.y*BCH;
    const int b  = blockIdx.z;
    const int w4 = tx*4;

    // per-row g for this thread's 4 output rows (reused across 8 channels)
    float4 G0[4], G1[4], G2[4], G3[4];
    #pragma unroll
    for (int j = 0; j < 4; j++) {
        const int gi = b*HW + (h0 + j)*WW + w4;
        G0[j] = *(const float4*)&d_g[0][gi];
        G1[j] = *(const float4*)&d_g[1][gi];
        G2[j] = *(const float4*)&d_g[2][gi];
        G3[j] = *(const float4*)&d_g[3][gi];
    }

    const float* tp = d_tmp + (size_t)b*CHW + (size_t)c0*HW + w4;
    float*       op = out   + (size_t)b*CHW + (size_t)c0*HW + w4;
    const float4 z4 = make_float4(0.f, 0.f, 0.f, 0.f);
    const bool interior = (h0 >= 3) && (h0 + 6 < HH);

    if (interior) {
        for (int c = 0; c < BCH; c++) {
            const float* p = tp + (size_t)c*HW + (h0 - 3)*WW;
            float4 wn[10];
            #pragma unroll
            for (int i = 0; i < 10; i++)
                wn[i] = *(const float4*)(p + i*WW);
            float* o = op + (size_t)c*HW + h0*WW;
            #pragma unroll
            for (int j = 0; j < 4; j++) {
                float4 v;
                v.x = fmaf(G0[j].x, wn[j].x+wn[j+6].x, fmaf(G1[j].x, wn[j+1].x+wn[j+5].x, fmaf(G2[j].x, wn[j+2].x+wn[j+4].x, G3[j].x*wn[j+3].x)));
                v.y = fmaf(G0[j].y, wn[j].y+wn[j+6].y, fmaf(G1[j].y, wn[j+1].y+wn[j+5].y, fmaf(G2[j].y, wn[j+2].y+wn[j+4].y, G3[j].y*wn[j+3].y)));
                v.z = fmaf(G0[j].z, wn[j].z+wn[j+6].z, fmaf(G1[j].z, wn[j+1].z+wn[j+5].z, fmaf(G2[j].z, wn[j+2].z+wn[j+4].z, G3[j].z*wn[j+3].z)));
                v.w = fmaf(G0[j].w, wn[j].w+wn[j+6].w, fmaf(G1[j].w, wn[j+1].w+wn[j+5].w, fmaf(G2[j].w, wn[j+2].w+wn[j+4].w, G3[j].w*wn[j+3].w)));
                *(float4*)(o + j*WW) = v;
            }
        }
    } else {
        bool ok[10];
        #pragma unroll
        for (int i = 0; i < 10; i++) {
            int r = h0 - 3 + i;
            ok[i] = (r >= 0) && (r < HH);
        }
        for (int c = 0; c < BCH; c++) {
            const float* p = tp + (size_t)c*HW + (h0 - 3)*WW;
            float4 wn[10];
            #pragma unroll
            for (int i = 0; i < 10; i++)
                wn[i] = ok[i] ? *(const float4*)(p + i*WW) : z4;
            float* o = op + (size_t)c*HW + h0*WW;
            #pragma unroll
            for (int j = 0; j < 4; j++) {
                float4 v;
                v.x = fmaf(G0[j].x, wn[j].x+wn[j+6].x, fmaf(G1[j].x, wn[j+1].x+wn[j+5].x, fmaf(G2[j].x, wn[j+2].x+wn[j+4].x, G3[j].x*wn[j+3].x)));
                v.y = fmaf(G0[j].y, wn[j].y+wn[j+6].y, fmaf(G1[j].y, wn[j+1].y+wn[j+5].y, fmaf(G2[j].y, wn[j+2].y+wn[j+4].y, G3[j].y*wn[j+3].y)));
                v.z = fmaf(G0[j].z, wn[j].z+wn[j+6].z, fmaf(G1[j].z, wn[j+1].z+wn[j+5].z, fmaf(G2[j].z, wn[j+2].z+wn[j+4].z, G3[j].z*wn[j+3].z)));
                v.w = fmaf(G0[j].w, wn[j].w+wn[j+6].w, fmaf(G1[j].w, wn[j+1].w+wn[j+5].w, fmaf(G2[j].w, wn[j+2].w+wn[j+4].w, G3[j].w*wn[j+3].w)));
                *(float4*)(o + j*WW) = v;
            }
        }
    }
}

extern "C" void kernel_launch(void* const* d_in, const int* in_sizes, int n_in,
                              void* d_out, int out_size) {
    const float* x = (const float*)d_in[0];
    float* out = (float*)d_out;

    init_minmax_kernel<<<1, 32>>>();

    edge_partial_kernel<<<dim3(HH/16, NSPLIT, BB), dim3(64, 4)>>>(x);

    edge_reduce_kernel<<<(BB*HW/4)/256, 256>>>();

    gauss_kernel<<<(BB*HW)/256, 256>>>();

    hblur_kernel<<<dim3(HH/4, CC/BCH, BB), dim3(64, 4)>>>(x);

    vblur_kernel<<<dim3(HH/16, CC/BCH, BB), dim3(64, 4)>>>(out);
}

// round 14
// speedup vs baseline: 1.1575x; 1.1575x over previous
#include <cuda_runtime.h>

#define BB 4
#define CC 64
#define HH 256
#define WW 256
#define HW (HH*WW)
#define CHW (CC*HW)

#define NSPLIT 8
#define ECH (CC/NSPLIT)   // 8 channels per edge block
#define SB 4              // channels staged per barrier pair in edge kernel

#define CHALF 32          // channels per blur half
#define BCH 4             // channels per blur block

#define SIGMA_MIN 0.6f
#define SIGMA_MAX 1.2f

// Scratch (static device allocations — no cudaMalloc allowed)
__device__ float d_edge[BB*HW];                  // 1 MB
__device__ float d_edge_part[NSPLIT][BB*HW];     // 8 MB partial channel-sums
__device__ float d_g[4][BB*HW];                  // 4 MB (symmetric taps)
__device__ float d_tmp[(size_t)BB*CHALF*HW];     // 32 MB tmp (reused per half; L2-resident)
__device__ unsigned int d_minmax[2*BB];          // per-batch {min,max} uint bits

__global__ void init_minmax_kernel() {
    int i = threadIdx.x;
    if (i < BB) {
        d_minmax[2*i]   = 0x7f800000u; // +inf
        d_minmax[2*i+1] = 0u;          // 0
    }
}

// Partial Sobel edge-energy sums over 8 channels per block.
// Block (64,4): 8-row x 256-col tile; 4 channels staged per barrier pair.
__global__ __launch_bounds__(256) void edge_partial_kernel(const float* __restrict__ x) {
    __shared__ float xs[SB][10][264];

    const int tx = threadIdx.x;
    const int ty = threadIdx.y;
    const int tid = ty*64 + tx;
    const int h0 = blockIdx.x*8;
    const int sp = blockIdx.y;
    const int b  = blockIdx.z;

    if (tid < SB*10) {
        int ch = tid / 10, r = tid % 10;
        xs[ch][r][3] = 0.f; xs[ch][r][260] = 0.f;
    }

    const float* xb = x + (size_t)b*CHW + (size_t)sp*ECH*HW;
    float acc[2][4] = {};

    for (int cb = 0; cb < ECH; cb += SB) {
        __syncthreads();
        #pragma unroll
        for (int k = 0; k < 10; k++) {
            int i  = tid + k*256;
            int ch = i / 640;
            int rm = i - ch*640;
            int r  = rm >> 6, q = rm & 63;
            int gh = h0 - 1 + r;
            float4 v = make_float4(0.f, 0.f, 0.f, 0.f);
            if (gh >= 0 && gh < HH)
                v = *(const float4*)(xb + (size_t)(cb + ch)*HW + gh*WW + q*4);
            *(float4*)&xs[ch][r][4 + q*4] = v;
        }
        __syncthreads();

        #pragma unroll
        for (int ch = 0; ch < SB; ch++) {
            #pragma unroll
            for (int rr = 0; rr < 2; rr++) {
                const int base = ty + rr*4;
                float d[3][4], s[3][4];
                #pragma unroll
                for (int r = 0; r < 3; r++) {
                    const float* row = &xs[ch][base + r][4 + 4*tx];
                    float  l = row[-1];
                    float4 m = *(const float4*)row;
                    float rt = row[4];
                    d[r][0] = m.y - l;    s[r][0] = l   + 2.f*m.x + m.y;
                    d[r][1] = m.z - m.x;  s[r][1] = m.x + 2.f*m.y + m.z;
                    d[r][2] = m.w - m.y;  s[r][2] = m.y + 2.f*m.z + m.w;
                    d[r][3] = rt  - m.z;  s[r][3] = m.z + 2.f*m.w + rt;
                }
                #pragma unroll
                for (int j = 0; j < 4; j++) {
                    float gx = d[0][j] + 2.f*d[1][j] + d[2][j];
                    float gy = s[2][j] - s[0][j];
                    acc[rr][j] = fmaf(gx, gx, acc[rr][j]);
                    acc[rr][j] = fmaf(gy, gy, acc[rr][j]);
                }
            }
        }
    }

    #pragma unroll
    for (int rr = 0; rr < 2; rr++) {
        const int h = h0 + ty + rr*4;
        float4 e = make_float4(acc[rr][0], acc[rr][1], acc[rr][2], acc[rr][3]);
        *(float4*)(d_edge_part[sp] + b*HW + h*WW + 4*tx) = e;
    }
}

// Sum partials -> edge; per-batch min/max via block reduce + uint atomics.
__global__ __launch_bounds__(256) void edge_reduce_kernel() {
    __shared__ float smin[8], smax[8];
    const int idx4 = blockIdx.x*256 + threadIdx.x;
    const int b = idx4 >> 14;

    float4 s = make_float4(0.f, 0.f, 0.f, 0.f);
    #pragma unroll
    for (int sp = 0; sp < NSPLIT; sp++) {
        float4 v = *(const float4*)(d_edge_part[sp] + (size_t)idx4*4);
        s.x += v.x; s.y += v.y; s.z += v.z; s.w += v.w;
    }
    s.x *= (1.f/64.f); s.y *= (1.f/64.f); s.z *= (1.f/64.f); s.w *= (1.f/64.f);
    *(float4*)(d_edge + (size_t)idx4*4) = s;

    float vmin = fminf(fminf(s.x, s.y), fminf(s.z, s.w));
    float vmax = fmaxf(fmaxf(s.x, s.y), fmaxf(s.z, s.w));
    #pragma unroll
    for (int o = 16; o; o >>= 1) {
        vmin = fminf(vmin, __shfl_xor_sync(0xffffffffu, vmin, o));
        vmax = fmaxf(vmax, __shfl_xor_sync(0xffffffffu, vmax, o));
    }
    const int wid = threadIdx.x >> 5, lane = threadIdx.x & 31;
    if (lane == 0) { smin[wid] = vmin; smax[wid] = vmax; }
    __syncthreads();
    if (threadIdx.x == 0) {
        float m = smin[0], M = smax[0];
        #pragma unroll
        for (int i = 1; i < 8; i++) { m = fminf(m, smin[i]); M = fmaxf(M, smax[i]); }
        atomicMin(&d_minmax[2*b],   __float_as_uint(m));
        atomicMax(&d_minmax[2*b+1], __float_as_uint(M));
    }
}

// Per-pixel normalized Gaussian taps. 1 expf per pixel; scalar = max parallelism.
__global__ __launch_bounds__(256) void gauss_kernel() {
    const int idx = blockIdx.x*256 + threadIdx.x;
    const int b = idx >> 16;   // HW per batch
    const float emin = __uint_as_float(d_minmax[2*b]);
    const float rden = __fdividef(1.f, __uint_as_float(d_minmax[2*b+1]) + 1e-6f);

    float e = (d_edge[idx] - emin) * rden;
    float s = SIGMA_MIN + (SIGMA_MAX - SIGMA_MIN)*e;
    float t = __fdividef(1.f, s);
    float inv = 0.5f*t*t;
    float w2 = __expf(-inv);
    float w2_2 = w2*w2;
    float w1 = w2_2*w2_2;
    float w0 = w1*w1*w2;
    float r = __fdividef(1.f, 2.f*(w0 + w1 + w2) + 1.f);
    d_g[0][idx] = w0*r;
    d_g[1][idx] = w1*r;
    d_g[2][idx] = w2*r;
    d_g[3][idx] = r;
}

// Horizontal pass: thread = 4 outputs x BCH channels; g in regs; no barriers.
// Operates on one CHALF-channel half; tmp holds only this half.
__global__ __launch_bounds__(256) void hblur_kernel(const float* __restrict__ x, int c_base) {
    const int tx = threadIdx.x;                 // 0..63
    const int h  = blockIdx.x*4 + threadIdx.y;
    const int cl = blockIdx.y*BCH;              // channel offset within half
    const int b  = blockIdx.z;
    const int w4 = tx*4;
    const int pidx = b*HW + h*WW + w4;

    const float4 G0 = *(const float4*)&d_g[0][pidx];
    const float4 G1 = *(const float4*)&d_g[1][pidx];
    const float4 G2 = *(const float4*)&d_g[2][pidx];
    const float4 G3 = *(const float4*)&d_g[3][pidx];

    const float* xr = x     + (size_t)b*CHW + (size_t)(c_base + cl)*HW + h*WW + w4;
    float*       tr = d_tmp + (size_t)b*CHALF*HW + (size_t)cl*HW + h*WW + w4;
    const bool hasL = (tx > 0), hasR = (tx < 63);
    const float4 z4 = make_float4(0.f, 0.f, 0.f, 0.f);

    #pragma unroll
    for (int c = 0; c < BCH; c++) {
        const float* p = xr + (size_t)c*HW;
        float4 m  = *(const float4*)p;
        float4 lf = hasL ? *(const float4*)(p - 4) : z4;
        float4 rf = hasR ? *(const float4*)(p + 4) : z4;
        float v0=lf.y, v1=lf.z, v2=lf.w, v3=m.x, v4=m.y, v5=m.z, v6=m.w, v7=rf.x, v8=rf.y, v9=rf.z;
        float4 o;
        o.x = fmaf(G0.x, v0+v6, fmaf(G1.x, v1+v5, fmaf(G2.x, v2+v4, G3.x*v3)));
        o.y = fmaf(G0.y, v1+v7, fmaf(G1.y, v2+v6, fmaf(G2.y, v3+v5, G3.y*v4)));
        o.z = fmaf(G0.z, v2+v8, fmaf(G1.z, v3+v7, fmaf(G2.z, v4+v6, G3.z*v5)));
        o.w = fmaf(G0.w, v3+v9, fmaf(G1.w, v4+v8, fmaf(G2.w, v5+v7, G3.w*v6)));
        *(float4*)(tr + (size_t)c*HW) = o;
    }
}

// Vertical pass: thread = 4 consecutive output rows x BCH channels.
// Per channel: 10-row register window (10 LDG.128) -> 4 outputs (4 STG.128).
// tmp half is L2-resident (32 MB).
__global__ __launch_bounds__(256) void vblur_kernel(float* __restrict__ out, int c_base) {
    const int tx = threadIdx.x;                      // 0..63 (column quad)
    const int ty = threadIdx.y;                      // 0..3 (4-row group)
    const int h0 = blockIdx.x*16 + ty*4;             // first output row
    const int cl = blockIdx.y*BCH;                   // channel offset within half
    const int b  = blockIdx.z;
    const int w4 = tx*4;

    // per-row g for this thread's 4 output rows (reused across BCH channels)
    float4 G0[4], G1[4], G2[4], G3[4];
    #pragma unroll
    for (int j = 0; j < 4; j++) {
        const int gi = b*HW + (h0 + j)*WW + w4;
        G0[j] = *(const float4*)&d_g[0][gi];
        G1[j] = *(const float4*)&d_g[1][gi];
        G2[j] = *(const float4*)&d_g[2][gi];
        G3[j] = *(const float4*)&d_g[3][gi];
    }

    const float* tp = d_tmp + (size_t)b*CHALF*HW + (size_t)cl*HW + w4;
    float*       op = out   + (size_t)b*CHW + (size_t)(c_base + cl)*HW + w4;
    const float4 z4 = make_float4(0.f, 0.f, 0.f, 0.f);
    const bool interior = (h0 >= 3) && (h0 + 6 < HH);

    if (interior) {
        #pragma unroll
        for (int c = 0; c < BCH; c++) {
            const float* p = tp + (size_t)c*HW + (h0 - 3)*WW;
            float4 wn[10];
            #pragma unroll
            for (int i = 0; i < 10; i++)
                wn[i] = *(const float4*)(p + i*WW);
            float* o = op + (size_t)c*HW + h0*WW;
            #pragma unroll
            for (int j = 0; j < 4; j++) {
                float4 v;
                v.x = fmaf(G0[j].x, wn[j].x+wn[j+6].x, fmaf(G1[j].x, wn[j+1].x+wn[j+5].x, fmaf(G2[j].x, wn[j+2].x+wn[j+4].x, G3[j].x*wn[j+3].x)));
                v.y = fmaf(G0[j].y, wn[j].y+wn[j+6].y, fmaf(G1[j].y, wn[j+1].y+wn[j+5].y, fmaf(G2[j].y, wn[j+2].y+wn[j+4].y, G3[j].y*wn[j+3].y)));
                v.z = fmaf(G0[j].z, wn[j].z+wn[j+6].z, fmaf(G1[j].z, wn[j+1].z+wn[j+5].z, fmaf(G2[j].z, wn[j+2].z+wn[j+4].z, G3[j].z*wn[j+3].z)));
                v.w = fmaf(G0[j].w, wn[j].w+wn[j+6].w, fmaf(G1[j].w, wn[j+1].w+wn[j+5].w, fmaf(G2[j].w, wn[j+2].w+wn[j+4].w, G3[j].w*wn[j+3].w)));
                *(float4*)(o + j*WW) = v;
            }
        }
    } else {
        bool ok[10];
        #pragma unroll
        for (int i = 0; i < 10; i++) {
            int r = h0 - 3 + i;
            ok[i] = (r >= 0) && (r < HH);
        }
        #pragma unroll
        for (int c = 0; c < BCH; c++) {
            const float* p = tp + (size_t)c*HW + (h0 - 3)*WW;
            float4 wn[10];
            #pragma unroll
            for (int i = 0; i < 10; i++)
                wn[i] = ok[i] ? *(const float4*)(p + i*WW) : z4;
            float* o = op + (size_t)c*HW + h0*WW;
            #pragma unroll
            for (int j = 0; j < 4; j++) {
                float4 v;
                v.x = fmaf(G0[j].x, wn[j].x+wn[j+6].x, fmaf(G1[j].x, wn[j+1].x+wn[j+5].x, fmaf(G2[j].x, wn[j+2].x+wn[j+4].x, G3[j].x*wn[j+3].x)));
                v.y = fmaf(G0[j].y, wn[j].y+wn[j+6].y, fmaf(G1[j].y, wn[j+1].y+wn[j+5].y, fmaf(G2[j].y, wn[j+2].y+wn[j+4].y, G3[j].y*wn[j+3].y)));
                v.z = fmaf(G0[j].z, wn[j].z+wn[j+6].z, fmaf(G1[j].z, wn[j+1].z+wn[j+5].z, fmaf(G2[j].z, wn[j+2].z+wn[j+4].z, G3[j].z*wn[j+3].z)));
                v.w = fmaf(G0[j].w, wn[j].w+wn[j+6].w, fmaf(G1[j].w, wn[j+1].w+wn[j+5].w, fmaf(G2[j].w, wn[j+2].w+wn[j+4].w, G3[j].w*wn[j+3].w)));
                *(float4*)(o + j*WW) = v;
            }
        }
    }
}

extern "C" void kernel_launch(void* const* d_in, const int* in_sizes, int n_in,
                              void* d_out, int out_size) {
    const float* x = (const float*)d_in[0];
    float* out = (float*)d_out;

    init_minmax_kernel<<<1, 32>>>();

    edge_partial_kernel<<<dim3(HH/8, NSPLIT, BB), dim3(64, 4)>>>(x);

    edge_reduce_kernel<<<(BB*HW/4)/256, 256>>>();

    gauss_kernel<<<(BB*HW)/256, 256>>>();

    for (int half = 0; half < 2; half++) {
        const int c_base = half * CHALF;
        hblur_kernel<<<dim3(HH/4, CHALF/BCH, BB), dim3(64, 4)>>>(x, c_base);
        vblur_kernel<<<dim3(HH/16, CHALF/BCH, BB), dim3(64, 4)>>>(out, c_base);
    }
}

// round 15
// speedup vs baseline: 1.2130x; 1.0480x over previous
#include <cuda_runtime.h>

#define BB 4
#define CC 64
#define HH 256
#define WW 256
#define HW (HH*WW)
#define CHW (CC*HW)

#define NSPLIT 8
#define ECH (CC/NSPLIT)   // 8 channels per edge block
#define SB 2              // channels staged per barrier pair in edge kernel
#define ETILE 16          // output rows per edge block
#define EROWS (ETILE+2)   // 18 staged rows incl. halo
#define BCH 8             // channels per blur block

#define SIGMA_MIN 0.6f
#define SIGMA_MAX 1.2f

// Scratch (static device allocations — no cudaMalloc allowed)
__device__ float d_edge[BB*HW];                  // 1 MB
__device__ float d_edge_part[NSPLIT][BB*HW];     // 8 MB partial channel-sums
__device__ float d_g[4][BB*HW];                  // 4 MB (symmetric taps)
__device__ float d_tmp[(size_t)BB*CHW];          // 64 MB horizontal-pass result
__device__ unsigned int d_minmax[2*BB];          // per-batch {min,max} uint bits

__global__ void init_minmax_kernel() {
    int i = threadIdx.x;
    if (i < BB) {
        d_minmax[2*i]   = 0x7f800000u; // +inf
        d_minmax[2*i+1] = 0u;          // 0
    }
}

// Partial Sobel edge-energy sums over 8 channels per block.
// v4: block (64,4) = 16-row x 256-col tile; thread owns 4 CONSECUTIVE output
// rows; 6-row d/s window computed once in regs, slid across the 4 outputs
// (18 LDS per 4 outputs). SB=2 channels staged per barrier pair (MLP 9).
__global__ __launch_bounds__(256) void edge_partial_kernel(const float* __restrict__ x) {
    __shared__ float xs[SB][EROWS][264];   // rows h0-1..h0+16; data cols [4..259], zero halo [3],[260]

    const int tx = threadIdx.x;            // 0..63 (column quad)
    const int ty = threadIdx.y;            // 0..3  (4-row group)
    const int tid = ty*64 + tx;
    const int h0 = blockIdx.x*ETILE;
    const int sp = blockIdx.y;             // channel split
    const int b  = blockIdx.z;

    if (tid < SB*EROWS) {
        int ch = tid / EROWS, r = tid % EROWS;
        xs[ch][r][3] = 0.f; xs[ch][r][260] = 0.f;
    }

    const float* xb = x + (size_t)b*CHW + (size_t)sp*ECH*HW;
    float acc[4][4] = {};

    for (int cb = 0; cb < ECH; cb += SB) {
        __syncthreads();
        // stage SB channels x 18 rows x 64 quads = 2304 quad tasks, 9/thread
        #pragma unroll
        for (int k = 0; k < 9; k++) {
            int i  = tid + k*256;
            int ch = i / (EROWS*64);
            int rm = i - ch*(EROWS*64);
            int r  = rm >> 6, q = rm & 63;
            int gh = h0 - 1 + r;
            float4 v = make_float4(0.f, 0.f, 0.f, 0.f);
            if (gh >= 0 && gh < HH)
                v = *(const float4*)(xb + (size_t)(cb + ch)*HW + gh*WW + q*4);
            *(float4*)&xs[ch][r][4 + q*4] = v;
        }
        __syncthreads();

        #pragma unroll
        for (int ch = 0; ch < SB; ch++) {
            // 6-row window: smem rows 4ty .. 4ty+5 (global h0+4ty-1 .. h0+4ty+4)
            float d[6][4], s[6][4];
            #pragma unroll
            for (int r = 0; r < 6; r++) {
                const float* row = &xs[ch][4*ty + r][4 + 4*tx];
                float  l = row[-1];
                float4 m = *(const float4*)row;
                float rt = row[4];
                d[r][0] = m.y - l;    s[r][0] = l   + 2.f*m.x + m.y;
                d[r][1] = m.z - m.x;  s[r][1] = m.x + 2.f*m.y + m.z;
                d[r][2] = m.w - m.y;  s[r][2] = m.y + 2.f*m.z + m.w;
                d[r][3] = rt  - m.z;  s[r][3] = m.z + 2.f*m.w + rt;
            }
            #pragma unroll
            for (int j = 0; j < 4; j++) {
                #pragma unroll
                for (int k = 0; k < 4; k++) {
                    float gx = d[j][k] + 2.f*d[j+1][k] + d[j+2][k];
                    float gy = s[j+2][k] - s[j][k];
                    acc[j][k] = fmaf(gx, gx, acc[j][k]);
                    acc[j][k] = fmaf(gy, gy, acc[j][k]);
                }
            }
        }
    }

    #pragma unroll
    for (int j = 0; j < 4; j++) {
        float4 e = make_float4(acc[j][0], acc[j][1], acc[j][2], acc[j][3]);
        *(float4*)(d_edge_part[sp] + b*HW + (h0 + 4*ty + j)*WW + 4*tx) = e;
    }
}

// Sum partials -> edge; per-batch min/max via block reduce + uint atomics.
__global__ __launch_bounds__(256) void edge_reduce_kernel() {
    __shared__ float smin[8], smax[8];
    const int idx4 = blockIdx.x*256 + threadIdx.x;
    const int b = idx4 >> 14;

    float4 s = make_float4(0.f, 0.f, 0.f, 0.f);
    #pragma unroll
    for (int sp = 0; sp < NSPLIT; sp++) {
        float4 v = *(const float4*)(d_edge_part[sp] + (size_t)idx4*4);
        s.x += v.x; s.y += v.y; s.z += v.z; s.w += v.w;
    }
    s.x *= (1.f/64.f); s.y *= (1.f/64.f); s.z *= (1.f/64.f); s.w *= (1.f/64.f);
    *(float4*)(d_edge + (size_t)idx4*4) = s;

    float vmin = fminf(fminf(s.x, s.y), fminf(s.z, s.w));
    float vmax = fmaxf(fmaxf(s.x, s.y), fmaxf(s.z, s.w));
    #pragma unroll
    for (int o = 16; o; o >>= 1) {
        vmin = fminf(vmin, __shfl_xor_sync(0xffffffffu, vmin, o));
        vmax = fmaxf(vmax, __shfl_xor_sync(0xffffffffu, vmax, o));
    }
    const int wid = threadIdx.x >> 5, lane = threadIdx.x & 31;
    if (lane == 0) { smin[wid] = vmin; smax[wid] = vmax; }
    __syncthreads();
    if (threadIdx.x == 0) {
        float m = smin[0], M = smax[0];
        #pragma unroll
        for (int i = 1; i < 8; i++) { m = fminf(m, smin[i]); M = fmaxf(M, smax[i]); }
        atomicMin(&d_minmax[2*b],   __float_as_uint(m));
        atomicMax(&d_minmax[2*b+1], __float_as_uint(M));
    }
}

// Per-pixel normalized Gaussian taps. 1 expf per pixel; scalar = max parallelism.
__global__ __launch_bounds__(256) void gauss_kernel() {
    const int idx = blockIdx.x*256 + threadIdx.x;
    const int b = idx >> 16;   // HW per batch
    const float emin = __uint_as_float(d_minmax[2*b]);
    const float rden = __fdividef(1.f, __uint_as_float(d_minmax[2*b+1]) + 1e-6f);

    float e = (d_edge[idx] - emin) * rden;
    float s = SIGMA_MIN + (SIGMA_MAX - SIGMA_MIN)*e;
    float t = __fdividef(1.f, s);
    float inv = 0.5f*t*t;
    float w2 = __expf(-inv);
    float w2_2 = w2*w2;
    float w1 = w2_2*w2_2;
    float w0 = w1*w1*w2;
    float r = __fdividef(1.f, 2.f*(w0 + w1 + w2) + 1.f);
    d_g[0][idx] = w0*r;
    d_g[1][idx] = w1*r;
    d_g[2][idx] = w2*r;
    d_g[3][idx] = r;
}

// Horizontal pass: thread = 4 outputs x 8 channels; g in regs; no barriers.
__global__ __launch_bounds__(256) void hblur_kernel(const float* __restrict__ x) {
    const int tx = threadIdx.x;                 // 0..63
    const int h  = blockIdx.x*4 + threadIdx.y;
    const int c0 = blockIdx.y*BCH;
    const int b  = blockIdx.z;
    const int w4 = tx*4;
    const int pidx = b*HW + h*WW + w4;

    const float4 G0 = *(const float4*)&d_g[0][pidx];
    const float4 G1 = *(const float4*)&d_g[1][pidx];
    const float4 G2 = *(const float4*)&d_g[2][pidx];
    const float4 G3 = *(const float4*)&d_g[3][pidx];

    const float* xr = x     + (size_t)b*CHW + (size_t)c0*HW + h*WW + w4;
    float*       tr = d_tmp + (size_t)b*CHW + (size_t)c0*HW + h*WW + w4;
    const bool hasL = (tx > 0), hasR = (tx < 63);
    const float4 z4 = make_float4(0.f, 0.f, 0.f, 0.f);

    #pragma unroll 2
    for (int c = 0; c < BCH; c++) {
        const float* p = xr + (size_t)c*HW;
        float4 m  = *(const float4*)p;
        float4 lf = hasL ? *(const float4*)(p - 4) : z4;
        float4 rf = hasR ? *(const float4*)(p + 4) : z4;
        float v0=lf.y, v1=lf.z, v2=lf.w, v3=m.x, v4=m.y, v5=m.z, v6=m.w, v7=rf.x, v8=rf.y, v9=rf.z;
        float4 o;
        o.x = fmaf(G0.x, v0+v6, fmaf(G1.x, v1+v5, fmaf(G2.x, v2+v4, G3.x*v3)));
        o.y = fmaf(G0.y, v1+v7, fmaf(G1.y, v2+v6, fmaf(G2.y, v3+v5, G3.y*v4)));
        o.z = fmaf(G0.z, v2+v8, fmaf(G1.z, v3+v7, fmaf(G2.z, v4+v6, G3.z*v5)));
        o.w = fmaf(G0.w, v3+v9, fmaf(G1.w, v4+v8, fmaf(G2.w, v5+v7, G3.w*v6)));
        *(float4*)(tr + (size_t)c*HW) = o;
    }
}

// Vertical pass: thread = 4 consecutive output rows x 8 channels.
// Per channel: 10-row register window (10 LDG.128) -> 4 outputs (4 STG.128).
__global__ __launch_bounds__(256) void vblur_kernel(float* __restrict__ out) {
    const int tx = threadIdx.x;                      // 0..63 (column quad)
    const int ty = threadIdx.y;                      // 0..3 (4-row group)
    const int h0 = blockIdx.x*16 + ty*4;             // first output row
    const int c0 = blockIdx.y*BCH;
    const int b  = blockIdx.z;
    const int w4 = tx*4;

    // per-row g for this thread's 4 output rows (reused across 8 channels)
    float4 G0[4], G1[4], G2[4], G3[4];
    #pragma unroll
    for (int j = 0; j < 4; j++) {
        const int gi = b*HW + (h0 + j)*WW + w4;
        G0[j] = *(const float4*)&d_g[0][gi];
        G1[j] = *(const float4*)&d_g[1][gi];
        G2[j] = *(const float4*)&d_g[2][gi];
        G3[j] = *(const float4*)&d_g[3][gi];
    }

    const float* tp = d_tmp + (size_t)b*CHW + (size_t)c0*HW + w4;
    float*       op = out   + (size_t)b*CHW + (size_t)c0*HW + w4;
    const float4 z4 = make_float4(0.f, 0.f, 0.f, 0.f);
    const bool interior = (h0 >= 3) && (h0 + 6 < HH);

    if (interior) {
        for (int c = 0; c < BCH; c++) {
            const float* p = tp + (size_t)c*HW + (h0 - 3)*WW;
            float4 wn[10];
            #pragma unroll
            for (int i = 0; i < 10; i++)
                wn[i] = *(const float4*)(p + i*WW);
            float* o = op + (size_t)c*HW + h0*WW;
            #pragma unroll
            for (int j = 0; j < 4; j++) {
                float4 v;
                v.x = fmaf(G0[j].x, wn[j].x+wn[j+6].x, fmaf(G1[j].x, wn[j+1].x+wn[j+5].x, fmaf(G2[j].x, wn[j+2].x+wn[j+4].x, G3[j].x*wn[j+3].x)));
                v.y = fmaf(G0[j].y, wn[j].y+wn[j+6].y, fmaf(G1[j].y, wn[j+1].y+wn[j+5].y, fmaf(G2[j].y, wn[j+2].y+wn[j+4].y, G3[j].y*wn[j+3].y)));
                v.z = fmaf(G0[j].z, wn[j].z+wn[j+6].z, fmaf(G1[j].z, wn[j+1].z+wn[j+5].z, fmaf(G2[j].z, wn[j+2].z+wn[j+4].z, G3[j].z*wn[j+3].z)));
                v.w = fmaf(G0[j].w, wn[j].w+wn[j+6].w, fmaf(G1[j].w, wn[j+1].w+wn[j+5].w, fmaf(G2[j].w, wn[j+2].w+wn[j+4].w, G3[j].w*wn[j+3].w)));
                *(float4*)(o + j*WW) = v;
            }
        }
    } else {
        bool ok[10];
        #pragma unroll
        for (int i = 0; i < 10; i++) {
            int r = h0 - 3 + i;
            ok[i] = (r >= 0) && (r < HH);
        }
        for (int c = 0; c < BCH; c++) {
            const float* p = tp + (size_t)c*HW + (h0 - 3)*WW;
            float4 wn[10];
            #pragma unroll
            for (int i = 0; i < 10; i++)
                wn[i] = ok[i] ? *(const float4*)(p + i*WW) : z4;
            float* o = op + (size_t)c*HW + h0*WW;
            #pragma unroll
            for (int j = 0; j < 4; j++) {
                float4 v;
                v.x = fmaf(G0[j].x, wn[j].x+wn[j+6].x, fmaf(G1[j].x, wn[j+1].x+wn[j+5].x, fmaf(G2[j].x, wn[j+2].x+wn[j+4].x, G3[j].x*wn[j+3].x)));
                v.y = fmaf(G0[j].y, wn[j].y+wn[j+6].y, fmaf(G1[j].y, wn[j+1].y+wn[j+5].y, fmaf(G2[j].y, wn[j+2].y+wn[j+4].y, G3[j].y*wn[j+3].y)));
                v.z = fmaf(G0[j].z, wn[j].z+wn[j+6].z, fmaf(G1[j].z, wn[j+1].z+wn[j+5].z, fmaf(G2[j].z, wn[j+2].z+wn[j+4].z, G3[j].z*wn[j+3].z)));
                v.w = fmaf(G0[j].w, wn[j].w+wn[j+6].w, fmaf(G1[j].w, wn[j+1].w+wn[j+5].w, fmaf(G2[j].w, wn[j+2].w+wn[j+4].w, G3[j].w*wn[j+3].w)));
                *(float4*)(o + j*WW) = v;
            }
        }
    }
}

extern "C" void kernel_launch(void* const* d_in, const int* in_sizes, int n_in,
                              void* d_out, int out_size) {
    const float* x = (const float*)d_in[0];
    float* out = (float*)d_out;

    init_minmax_kernel<<<1, 32>>>();

    edge_partial_kernel<<<dim3(HH/ETILE, NSPLIT, BB), dim3(64, 4)>>>(x);

    edge_reduce_kernel<<<(BB*HW/4)/256, 256>>>();

    gauss_kernel<<<(BB*HW)/256, 256>>>();

    hblur_kernel<<<dim3(HH/4, CC/BCH, BB), dim3(64, 4)>>>(x);

    vblur_kernel<<<dim3(HH/16, CC/BCH, BB), dim3(64, 4)>>>(out);
}

// round 17
// speedup vs baseline: 1.2746x; 1.0508x over previous
#include <cuda_runtime.h>

#define BB 4
#define CC 64
#define HH 256
#define WW 256
#define HW (HH*WW)
#define CHW (CC*HW)

#define NSPLIT 8
#define ECH (CC/NSPLIT)   // 8 channels per edge block
#define SB 2              // channels staged per barrier pair in edge kernel
#define ETILE 16          // output rows per edge block
#define EROWS (ETILE+2)   // 18 staged rows incl. halo
#define BCH 8             // channels per blur block

#define RBLK 64           // edge_reduce blocks per batch

#define SIGMA_MIN 0.6f
#define SIGMA_MAX 1.2f

// Scratch (static device allocations — no cudaMalloc allowed)
__device__ float d_edge[BB*HW];                  // 1 MB normalizable edge energy
__device__ float d_edge_part[NSPLIT][BB*HW];     // 8 MB partial channel-sums
__device__ float d_tmp[(size_t)BB*CHW];          // 64 MB horizontal-pass result
__device__ float d_bmm[2][BB*RBLK];              // per-reduce-block {min,max} (no init needed)

// Per-pixel Gaussian taps from raw edge energy (symmetric: g0,g1,g2,center).
__device__ __forceinline__ void gauss_taps(float e_raw, float emin, float rden,
                                           float& g0, float& g1, float& g2, float& g3) {
    float e = (e_raw - emin) * rden;
    float s = SIGMA_MIN + (SIGMA_MAX - SIGMA_MIN)*e;
    float t = __fdividef(1.f, s);
    float inv = 0.5f*t*t;
    float w2 = __expf(-inv);
    float w2_2 = w2*w2;
    float w1 = w2_2*w2_2;
    float w0 = w1*w1*w2;
    float r = __fdividef(1.f, 2.f*(w0 + w1 + w2) + 1.f);
    g0 = w0*r; g1 = w1*r; g2 = w2*r; g3 = r;
}

// Block-start reduce of the 64 per-batch {min,max} slots; broadcast via smem.
// Returns emin in smm[0], rden in smm[1]. One warp + one barrier.
__device__ __forceinline__ void load_minmax(int b, int tid, float* smm) {
    if (tid < 32) {
        float mn = fminf(d_bmm[0][b*RBLK + tid], d_bmm[0][b*RBLK + 32 + tid]);
        float mx = fmaxf(d_bmm[1][b*RBLK + tid], d_bmm[1][b*RBLK + 32 + tid]);
        #pragma unroll
        for (int o = 16; o; o >>= 1) {
            mn = fminf(mn, __shfl_xor_sync(0xffffffffu, mn, o));
            mx = fmaxf(mx, __shfl_xor_sync(0xffffffffu, mx, o));
        }
        if (tid == 0) {
            smm[0] = mn;
            smm[1] = __fdividef(1.f, mx + 1e-6f);
        }
    }
    __syncthreads();
}

// Partial Sobel edge-energy sums over 8 channels per block.
// Block (64,4) = 16-row x 256-col tile; thread owns 4 consecutive output rows;
// 6-row d/s window in regs slid across the 4 outputs. SB=2 staged per barrier.
__global__ __launch_bounds__(256) void edge_partial_kernel(const float* __restrict__ x) {
    __shared__ float xs[SB][EROWS][264];

    const int tx = threadIdx.x;            // 0..63 (column quad)
    const int ty = threadIdx.y;            // 0..3  (4-row group)
    const int tid = ty*64 + tx;
    const int h0 = blockIdx.x*ETILE;
    const int sp = blockIdx.y;             // channel split
    const int b  = blockIdx.z;

    if (tid < SB*EROWS) {
        int ch = tid / EROWS, r = tid % EROWS;
        xs[ch][r][3] = 0.f; xs[ch][r][260] = 0.f;
    }

    const float* xb = x + (size_t)b*CHW + (size_t)sp*ECH*HW;
    float acc[4][4] = {};

    for (int cb = 0; cb < ECH; cb += SB) {
        __syncthreads();
        #pragma unroll
        for (int k = 0; k < 9; k++) {
            int i  = tid + k*256;
            int ch = i / (EROWS*64);
            int rm = i - ch*(EROWS*64);
            int r  = rm >> 6, q = rm & 63;
            int gh = h0 - 1 + r;
            float4 v = make_float4(0.f, 0.f, 0.f, 0.f);
            if (gh >= 0 && gh < HH)
                v = *(const float4*)(xb + (size_t)(cb + ch)*HW + gh*WW + q*4);
            *(float4*)&xs[ch][r][4 + q*4] = v;
        }
        __syncthreads();

        #pragma unroll
        for (int ch = 0; ch < SB; ch++) {
            float d[6][4], s[6][4];
            #pragma unroll
            for (int r = 0; r < 6; r++) {
                const float* row = &xs[ch][4*ty + r][4 + 4*tx];
                float  l = row[-1];
                float4 m = *(const float4*)row;
                float rt = row[4];
                d[r][0] = m.y - l;    s[r][0] = l   + 2.f*m.x + m.y;
                d[r][1] = m.z - m.x;  s[r][1] = m.x + 2.f*m.y + m.z;
                d[r][2] = m.w - m.y;  s[r][2] = m.y + 2.f*m.z + m.w;
                d[r][3] = rt  - m.z;  s[r][3] = m.z + 2.f*m.w + rt;
            }
            #pragma unroll
            for (int j = 0; j < 4; j++) {
                #pragma unroll
                for (int k = 0; k < 4; k++) {
                    float gx = d[j][k] + 2.f*d[j+1][k] + d[j+2][k];
                    float gy = s[j+2][k] - s[j][k];
                    acc[j][k] = fmaf(gx, gx, acc[j][k]);
                    acc[j][k] = fmaf(gy, gy, acc[j][k]);
                }
            }
        }
    }

    #pragma unroll
    for (int j = 0; j < 4; j++) {
        float4 e = make_float4(acc[j][0], acc[j][1], acc[j][2], acc[j][3]);
        *(float4*)(d_edge_part[sp] + b*HW + (h0 + 4*ty + j)*WW + 4*tx) = e;
    }
}

// Sum partials -> edge; per-BLOCK min/max written to fixed slots (no atomics,
// no init kernel; every slot written every run => deterministic).
__global__ __launch_bounds__(256) void edge_reduce_kernel() {
    __shared__ float smin[8], smax[8];
    const int idx4 = blockIdx.x*256 + threadIdx.x;

    float4 s = make_float4(0.f, 0.f, 0.f, 0.f);
    #pragma unroll
    for (int sp = 0; sp < NSPLIT; sp++) {
        float4 v = *(const float4*)(d_edge_part[sp] + (size_t)idx4*4);
        s.x += v.x; s.y += v.y; s.z += v.z; s.w += v.w;
    }
    s.x *= (1.f/64.f); s.y *= (1.f/64.f); s.z *= (1.f/64.f); s.w *= (1.f/64.f);
    *(float4*)(d_edge + (size_t)idx4*4) = s;

    float vmin = fminf(fminf(s.x, s.y), fminf(s.z, s.w));
    float vmax = fmaxf(fmaxf(s.x, s.y), fmaxf(s.z, s.w));
    #pragma unroll
    for (int o = 16; o; o >>= 1) {
        vmin = fminf(vmin, __shfl_xor_sync(0xffffffffu, vmin, o));
        vmax = fmaxf(vmax, __shfl_xor_sync(0xffffffffu, vmax, o));
    }
    const int wid = threadIdx.x >> 5, lane = threadIdx.x & 31;
    if (lane == 0) { smin[wid] = vmin; smax[wid] = vmax; }
    __syncthreads();
    if (threadIdx.x == 0) {
        float m = smin[0], M = smax[0];
        #pragma unroll
        for (int i = 1; i < 8; i++) { m = fminf(m, smin[i]); M = fmaxf(M, smax[i]); }
        d_bmm[0][blockIdx.x] = m;
        d_bmm[1][blockIdx.x] = M;
    }
}

// Horizontal pass: thread = 4 outputs x 8 channels; taps computed inline from
// d_edge (1 LDG.128 + 3 MUFU per 4 px, amortized over 8 channels).
__global__ __launch_bounds__(256) void hblur_kernel(const float* __restrict__ x) {
    __shared__ float smm[2];
    const int tx = threadIdx.x;                 // 0..63
    const int ty = threadIdx.y;
    const int tid = ty*64 + tx;
    const int h  = blockIdx.x*4 + ty;
    const int c0 = blockIdx.y*BCH;
    const int b  = blockIdx.z;
    const int w4 = tx*4;
    const int pidx = b*HW + h*WW + w4;

    load_minmax(b, tid, smm);
    const float emin = smm[0], rden = smm[1];

    const float4 e4 = *(const float4*)&d_edge[pidx];
    float4 G0, G1, G2, G3;
    gauss_taps(e4.x, emin, rden, G0.x, G1.x, G2.x, G3.x);
    gauss_taps(e4.y, emin, rden, G0.y, G1.y, G2.y, G3.y);
    gauss_taps(e4.z, emin, rden, G0.z, G1.z, G2.z, G3.z);
    gauss_taps(e4.w, emin, rden, G0.w, G1.w, G2.w, G3.w);

    const float* xr = x     + (size_t)b*CHW + (size_t)c0*HW + h*WW + w4;
    float*       tr = d_tmp + (size_t)b*CHW + (size_t)c0*HW + h*WW + w4;
    const bool hasL = (tx > 0), hasR = (tx < 63);
    const float4 z4 = make_float4(0.f, 0.f, 0.f, 0.f);

    #pragma unroll 2
    for (int c = 0; c < BCH; c++) {
        const float* p = xr + (size_t)c*HW;
        float4 m  = *(const float4*)p;
        float4 lf = hasL ? *(const float4*)(p - 4) : z4;
        float4 rf = hasR ? *(const float4*)(p + 4) : z4;
        float v0=lf.y, v1=lf.z, v2=lf.w, v3=m.x, v4=m.y, v5=m.z, v6=m.w, v7=rf.x, v8=rf.y, v9=rf.z;
        float4 o;
        o.x = fmaf(G0.x, v0+v6, fmaf(G1.x, v1+v5, fmaf(G2.x, v2+v4, G3.x*v3)));
        o.y = fmaf(G0.y, v1+v7, fmaf(G1.y, v2+v6, fmaf(G2.y, v3+v5, G3.y*v4)));
        o.z = fmaf(G0.z, v2+v8, fmaf(G1.z, v3+v7, fmaf(G2.z, v4+v6, G3.z*v5)));
        o.w = fmaf(G0.w, v3+v9, fmaf(G1.w, v4+v8, fmaf(G2.w, v5+v7, G3.w*v6)));
        *(float4*)(tr + (size_t)c*HW) = o;
    }
}

// Vertical pass: thread = 4 consecutive output rows x 8 channels; taps inline.
// Per channel: 10-row register window (10 LDG.128) -> 4 outputs (4 STG.128).
__global__ __launch_bounds__(256) void vblur_kernel(float* __restrict__ out) {
    __shared__ float smm[2];
    const int tx = threadIdx.x;                      // 0..63 (column quad)
    const int ty = threadIdx.y;                      // 0..3 (4-row group)
    const int tid = ty*64 + tx;
    const int h0 = blockIdx.x*16 + ty*4;             // first output row
    const int c0 = blockIdx.y*BCH;
    const int b  = blockIdx.z;
    const int w4 = tx*4;

    load_minmax(b, tid, smm);
    const float emin = smm[0], rden = smm[1];

    // per-row taps for this thread's 4 output rows (reused across 8 channels)
    float4 G0[4], G1[4], G2[4], G3[4];
    #pragma unroll
    for (int j = 0; j < 4; j++) {
        const float4 e4 = *(const float4*)&d_edge[b*HW + (h0 + j)*WW + w4];
        gauss_taps(e4.x, emin, rden, G0[j].x, G1[j].x, G2[j].x, G3[j].x);
        gauss_taps(e4.y, emin, rden, G0[j].y, G1[j].y, G2[j].y, G3[j].y);
        gauss_taps(e4.z, emin, rden, G0[j].z, G1[j].z, G2[j].z, G3[j].z);
        gauss_taps(e4.w, emin, rden, G0[j].w, G1[j].w, G2[j].w, G3[j].w);
    }

    const float* tp = d_tmp + (size_t)b*CHW + (size_t)c0*HW + w4;
    float*       op = out   + (size_t)b*CHW + (size_t)c0*HW + w4;
    const float4 z4 = make_float4(0.f, 0.f, 0.f, 0.f);
    const bool interior = (h0 >= 3) && (h0 + 6 < HH);

    if (interior) {
        for (int c = 0; c < BCH; c++) {
            const float* p = tp + (size_t)c*HW + (h0 - 3)*WW;
            float4 wn[10];
            #pragma unroll
            for (int i = 0; i < 10; i++)
                wn[i] = *(const float4*)(p + i*WW);
            float* o = op + (size_t)c*HW + h0*WW;
            #pragma unroll
            for (int j = 0; j < 4; j++) {
                float4 v;
                v.x = fmaf(G0[j].x, wn[j].x+wn[j+6].x, fmaf(G1[j].x, wn[j+1].x+wn[j+5].x, fmaf(G2[j].x, wn[j+2].x+wn[j+4].x, G3[j].x*wn[j+3].x)));
                v.y = fmaf(G0[j].y, wn[j].y+wn[j+6].y, fmaf(G1[j].y, wn[j+1].y+wn[j+5].y, fmaf(G2[j].y, wn[j+2].y+wn[j+4].y, G3[j].y*wn[j+3].y)));
                v.z = fmaf(G0[j].z, wn[j].z+wn[j+6].z, fmaf(G1[j].z, wn[j+1].z+wn[j+5].z, fmaf(G2[j].z, wn[j+2].z+wn[j+4].z, G3[j].z*wn[j+3].z)));
                v.w = fmaf(G0[j].w, wn[j].w+wn[j+6].w, fmaf(G1[j].w, wn[j+1].w+wn[j+5].w, fmaf(G2[j].w, wn[j+2].w+wn[j+4].w, G3[j].w*wn[j+3].w)));
                *(float4*)(o + j*WW) = v;
            }
        }
    } else {
        bool ok[10];
        #pragma unroll
        for (int i = 0; i < 10; i++) {
            int r = h0 - 3 + i;
            ok[i] = (r >= 0) && (r < HH);
        }
        for (int c = 0; c < BCH; c++) {
            const float* p = tp + (size_t)c*HW + (h0 - 3)*WW;
            float4 wn[10];
            #pragma unroll
            for (int i = 0; i < 10; i++)
                wn[i] = ok[i] ? *(const float4*)(p + i*WW) : z4;
            float* o = op + (size_t)c*HW + h0*WW;
            #pragma unroll
            for (int j = 0; j < 4; j++) {
                float4 v;
                v.x = fmaf(G0[j].x, wn[j].x+wn[j+6].x, fmaf(G1[j].x, wn[j+1].x+wn[j+5].x, fmaf(G2[j].x, wn[j+2].x+wn[j+4].x, G3[j].x*wn[j+3].x)));
                v.y = fmaf(G0[j].y, wn[j].y+wn[j+6].y, fmaf(G1[j].y, wn[j+1].y+wn[j+5].y, fmaf(G2[j].y, wn[j+2].y+wn[j+4].y, G3[j].y*wn[j+3].y)));
                v.z = fmaf(G0[j].z, wn[j].z+wn[j+6].z, fmaf(G1[j].z, wn[j+1].z+wn[j+5].z, fmaf(G2[j].z, wn[j+2].z+wn[j+4].z, G3[j].z*wn[j+3].z)));
                v.w = fmaf(G0[j].w, wn[j].w+wn[j+6].w, fmaf(G1[j].w, wn[j+1].w+wn[j+5].w, fmaf(G2[j].w, wn[j+2].w+wn[j+4].w, G3[j].w*wn[j+3].w)));
                *(float4*)(o + j*WW) = v;
            }
        }
    }
}

extern "C" void kernel_launch(void* const* d_in, const int* in_sizes, int n_in,
                              void* d_out, int out_size) {
    const float* x = (const float*)d_in[0];
    float* out = (float*)d_out;

    edge_partial_kernel<<<dim3(HH/ETILE, NSPLIT, BB), dim3(64, 4)>>>(x);

    edge_reduce_kernel<<<BB*RBLK, 256>>>();

    hblur_kernel<<<dim3(HH/4, CC/BCH, BB), dim3(64, 4)>>>(x);

    vblur_kernel<<<dim3(HH/16, CC/BCH, BB), dim3(64, 4)>>>(out);
}